// round 11
// baseline (speedup 1.0000x reference)
#include <cuda_runtime.h>
#include <cuda_fp16.h>
#include <cstdint>

// ---------------------------------------------------------------------------
// RxnPredictor: dual D-MPNN graph conv + mol pooling + reaction MLP
// R10: 3-stage cp.async pipeline (B via LDGSTS 2 ahead, A gather 2-deep in
// regs) + src/tgt graphs fused into single launches (15 -> 8 kernels).
// ---------------------------------------------------------------------------

#define MAXB  200000
#define HDIM  256
#define NMOLS 2048
#define NEI   10
#define WSTR  352          // padded K stride for pre-split weights

__device__ float g_nih [2][MAXB * HDIM];
__device__ float g_msgA[2][MAXB * HDIM];
__device__ float g_msgB[2][MAXB * HDIM];
__device__ float g_mol [2][NMOLS * HDIM];
__device__ __half g_Wb[6 * 256 * WSTR];   // big halves, 6 matrices
__device__ __half g_Ws[6 * 256 * WSTR];   // small halves

struct GArgs {
    const float* src; const int* graph;
    const __half* Wb; const __half* Ws;
    const float* extra; const float* bias;
    float* out; float* out2; int M;
};

// ---------------------------------------------------------------------------
// helpers
// ---------------------------------------------------------------------------
__device__ __forceinline__ uint32_t pack_h2(__half lo, __half hi) {
    __half2 h = __halves2half2(lo, hi);
    return *reinterpret_cast<uint32_t*>(&h);
}
__device__ __forceinline__ void split2(float x, float y, uint32_t& b, uint32_t& s) {
    __half hx = __float2half_rn(x), hy = __float2half_rn(y);
    float rx = x - __half2float(hx), ry = y - __half2float(hy);
    b = pack_h2(hx, hy);
    s = pack_h2(__float2half_rn(rx), __float2half_rn(ry));
}
__device__ __forceinline__ void mma_f16(float* d, const uint32_t* a,
                                        uint32_t b0, uint32_t b1) {
    asm volatile(
        "mma.sync.aligned.m16n8k16.row.col.f32.f16.f16.f32 "
        "{%0,%1,%2,%3}, {%4,%5,%6,%7}, {%8,%9}, {%0,%1,%2,%3};"
        : "+f"(d[0]), "+f"(d[1]), "+f"(d[2]), "+f"(d[3])
        : "r"(a[0]), "r"(a[1]), "r"(a[2]), "r"(a[3]), "r"(b0), "r"(b1));
}
__device__ __forceinline__ void ldsm_x4(uint32_t* r, uint32_t addr) {
    asm volatile("ldmatrix.sync.aligned.m8n8.x4.shared.b16 {%0,%1,%2,%3}, [%4];"
                 : "=r"(r[0]), "=r"(r[1]), "=r"(r[2]), "=r"(r[3]) : "r"(addr));
}
__device__ __forceinline__ uint32_t smem_u32(const void* p) {
    uint32_t a;
    asm("{ .reg .u64 t; cvta.to.shared.u64 t, %1; cvt.u32.u64 %0, t; }"
        : "=r"(a) : "l"(p));
    return a;
}
__device__ __forceinline__ void cp_async16(uint32_t smem, const void* g) {
    asm volatile("cp.async.cg.shared.global [%0], [%1], 16;"
                 :: "r"(smem), "l"(g) : "memory");
}
#define CP_COMMIT() asm volatile("cp.async.commit_group;" ::: "memory")
#define CP_WAIT(n)  asm volatile("cp.async.wait_group %0;" :: "n"(n) : "memory")

// ---------------------------------------------------------------------------
// Fused weight pre-split (slots 0..5 = Wi_s,Wh_s,Wo_s,Wi_t,Wh_t,Wo_t).
// Wo permutation: [gather(256) | fatoms(82)].
// ---------------------------------------------------------------------------
__global__ void split_all_w_kernel(const float* __restrict__ Wi_s, const float* __restrict__ Wh_s,
                                   const float* __restrict__ Wo_s, const float* __restrict__ Wi_t,
                                   const float* __restrict__ Wh_t, const float* __restrict__ Wo_t,
                                   __half* __restrict__ Wb, __half* __restrict__ Ws)
{
    const int slot = blockIdx.y;
    int i = blockIdx.x * 256 + threadIdx.x;
    if (i >= 256 * WSTR) return;
    int n = i / WSTR, k = i % WSTR;
    const float* W; int Ksrc; int perm;
    switch (slot) {
        case 0: W = Wi_s; Ksrc = 88;  perm = 0; break;
        case 1: W = Wh_s; Ksrc = 256; perm = 0; break;
        case 2: W = Wo_s; Ksrc = 338; perm = 1; break;
        case 3: W = Wi_t; Ksrc = 88;  perm = 0; break;
        case 4: W = Wh_t; Ksrc = 256; perm = 0; break;
        default: W = Wo_t; Ksrc = 338; perm = 1; break;
    }
    float v = 0.f;
    if (perm) {
        if (k < 256)      v = W[n * 338 + 82 + k];
        else if (k < 338) v = W[n * 338 + (k - 256)];
    } else if (k < Ksrc) {
        v = W[n * Ksrc + k];
    }
    __half hb = __float2half_rn(v);
    size_t o = (size_t)slot * 256 * WSTR + i;
    Wb[o] = hb;
    Ws[o] = __float2half_rn(v - __half2float(hb));
}

// ---------------------------------------------------------------------------
// 3xFP16 GEMM, dual-graph fused, 3-stage pipeline.
// Block 512 thr, BM=128, BN=256, BK=16. Warp grid 4(m) x 4(n).
// MODE 0: dense A (Kd=88); MODE 1: gather (K=256); MODE 2: [gather|fatoms].
// ---------------------------------------------------------------------------
#define BM 128
#define AROW 12
#define NST 3
#define A_SZ (BM * AROW)
#define B_SZ (256 * AROW)
#define A_BIG0 0
#define A_SML0 (NST * A_SZ)
#define B_BIG0 (2 * NST * A_SZ)
#define B_SML0 (2 * NST * A_SZ + NST * B_SZ)
#define SIDX_OFF (2 * NST * A_SZ + 2 * NST * B_SZ)
#define SMEM_U32 (SIDX_OFF + BM * NEI)
#define SMEM_BYTES (SMEM_U32 * 4)

template <int MODE>
__global__ __launch_bounds__(512)
void h16_gemm_kernel(GArgs ga0, GArgs ga1, int nblk0, int nk, int Kd, int max_nei)
{
    extern __shared__ uint32_t SMX[];
    uint32_t* SM = SMX;
    int* sIdx = (int*)(SM + SIDX_OFF);

    const bool second = (blockIdx.x >= nblk0);
    const GArgs G = second ? ga1 : ga0;
    const int bx = second ? (blockIdx.x - (unsigned)nblk0) : blockIdx.x;
    const float* __restrict__ src   = G.src;
    const int*   __restrict__ graph = G.graph;
    const __half* __restrict__ Wb   = G.Wb;
    const __half* __restrict__ Ws   = G.Ws;
    const float* __restrict__ extra = G.extra;
    const float* __restrict__ bias  = G.bias;
    float* __restrict__ out  = G.out;
    float* __restrict__ out2 = G.out2;
    const int M = G.M;

    const int t    = threadIdx.x;
    const int lane = t & 31;
    const int wid  = t >> 5;
    const int gid  = lane >> 2;
    const int tig  = lane & 3;
    const int wm0  = (wid & 3) * 32;
    const int wn0  = (wid >> 2) * 64;
    const int m0   = bx * BM;
    const int r    = t >> 2;          // A row (0..127)
    const int q    = t & 3;           // A k-quad
    const int bnn  = t >> 1;          // B row (0..255)
    const int bpt  = t & 1;           // B half-row part

    if (MODE != 0) {
        for (int i = t; i < BM * NEI; i += 512) {
            int rr = i / NEI, j = i % NEI;
            int m = m0 + rr;
            sIdx[i] = (m < M && j < max_nei) ? graph[m * max_nei + j] : -1;
        }
    }
    __syncthreads();

    // ldmatrix lane addresses (stage 0; stage offset added per iteration)
    const uint32_t smbase = smem_u32(SM);
    const int g8 = lane & 7;
    uint32_t aAddr[2];
#pragma unroll
    for (int ma = 0; ma < 2; ma++) {
        int row = wm0 + ma * 16 + g8 + ((lane >> 3) & 1) * 8;
        int byo = ((lane >> 4) & 1) * 16;
        aAddr[ma] = smbase + (uint32_t)(row * AROW) * 4u + byo;
    }
    uint32_t bAddr[4];
#pragma unroll
    for (int pa = 0; pa < 4; pa++) {
        int col = wn0 + pa * 16 + ((lane >> 4) & 1) * 8 + g8;
        int byo = ((lane >> 3) & 1) * 16;
        bAddr[pa] = smbase + (uint32_t)(B_BIG0 + col * AROW) * 4u + byo;
    }
    // per-thread smem write addresses
    const uint32_t aStBig = smbase + (uint32_t)(A_BIG0 + r * AROW + q * 2) * 4u;
    const uint32_t aStSml = smbase + (uint32_t)(A_SML0 + r * AROW + q * 2) * 4u;
    const uint32_t bStBig = smbase + (uint32_t)(B_BIG0 + bnn * AROW + bpt * 4) * 4u;
    const uint32_t bStSml = smbase + (uint32_t)(B_SML0 + bnn * AROW + bpt * 4) * 4u;

    float acc[2][8][4];
#pragma unroll
    for (int a = 0; a < 2; a++)
#pragma unroll
        for (int b = 0; b < 8; b++)
#pragma unroll
            for (int c = 0; c < 4; c++) acc[a][b][c] = 0.f;

    // ---- pipeline helpers ----
    auto load_B = [&](int kb, int st) {
        const size_t bo = (size_t)bnn * WSTR + kb * 16 + bpt * 8;
        cp_async16(bStBig + (uint32_t)(st * B_SZ) * 4u, Wb + bo);
        cp_async16(bStSml + (uint32_t)(st * B_SZ) * 4u, Ws + bo);
    };
    auto gather_A = [&](int kb, float4& av) {
        const int k0 = kb * 16;
        av = make_float4(0.f, 0.f, 0.f, 0.f);
        const int m = m0 + r;
        if (m < M) {
            if (MODE == 0) {
                const int k = k0 + q * 4;
                if (k + 3 < Kd)
                    av = *(const float4*)(src + (size_t)m * Kd + k);
            } else if (MODE == 1 || (MODE == 2 && k0 < 256)) {
                const float4* bp = (const float4*)src + (k0 >> 2) + q;
                const int* ip = sIdx + r * NEI;
                float4 v0, v1, v2, v3, v4;
#pragma unroll
                for (int w = 0; w < 2; w++) {
                    int s0 = ip[w * 5 + 0], s1 = ip[w * 5 + 1], s2 = ip[w * 5 + 2];
                    int s3 = ip[w * 5 + 3], s4 = ip[w * 5 + 4];
                    v0 = (s0 >= 0) ? bp[s0 * 64] : make_float4(0, 0, 0, 0);
                    v1 = (s1 >= 0) ? bp[s1 * 64] : make_float4(0, 0, 0, 0);
                    v2 = (s2 >= 0) ? bp[s2 * 64] : make_float4(0, 0, 0, 0);
                    v3 = (s3 >= 0) ? bp[s3 * 64] : make_float4(0, 0, 0, 0);
                    v4 = (s4 >= 0) ? bp[s4 * 64] : make_float4(0, 0, 0, 0);
                    av.x += v0.x + v1.x + v2.x + v3.x + v4.x;
                    av.y += v0.y + v1.y + v2.y + v3.y + v4.y;
                    av.z += v0.z + v1.z + v2.z + v3.z + v4.z;
                    av.w += v0.w + v1.w + v2.w + v3.w + v4.w;
                }
            } else {  // MODE 2 tail: fatoms columns
                float tmpv[4];
#pragma unroll
                for (int c = 0; c < 4; c++) {
                    int kk = k0 + q * 4 + c - 256;
                    tmpv[c] = (kk < 82) ? extra[m * 82 + kk] : 0.f;
                }
                av = make_float4(tmpv[0], tmpv[1], tmpv[2], tmpv[3]);
            }
        }
    };
    auto store_A = [&](const float4& av, int st) {
        uint32_t b0, s0, b1, s1;
        split2(av.x, av.y, b0, s0);
        split2(av.z, av.w, b1, s1);
        const uint32_t off = (uint32_t)(st * A_SZ) * 4u;
        *(uint2*)(uintptr_t)0; // placeholder removed below
        // write via generic pointers derived from SM array (same addresses)
        uint32_t* Ab = SM + A_BIG0 + st * A_SZ;
        uint32_t* As = SM + A_SML0 + st * A_SZ;
        *(uint2*)&Ab[r * AROW + q * 2] = make_uint2(b0, b1);
        *(uint2*)&As[r * AROW + q * 2] = make_uint2(s0, s1);
        (void)off; (void)aStBig; (void)aStSml;
    };

    // ---- prologue: B(0),B(1) via cp.async; A(0),A(1) in regs ----
    float4 av, av2;
    load_B(0, 0); CP_COMMIT();
    load_B(1, 1); CP_COMMIT();
    gather_A(0, av);
    gather_A(1, av2);
    store_A(av, 0);
    av = av2;
    CP_WAIT(1);
    __syncthreads();

    // ---- main loop ----
    for (int kb = 0; kb < nk; kb++) {
        const int st = kb % NST;
        const bool deep = (kb + 2 < nk);
        if (deep) {
            load_B(kb + 2, (kb + 2) % NST); CP_COMMIT();
            gather_A(kb + 2, av2);
        }

        const uint32_t aoff = (uint32_t)(st * A_SZ) * 4u;
        const uint32_t boff = (uint32_t)(st * B_SZ) * 4u;
        uint32_t afb[2][4], afs[2][4];
#pragma unroll
        for (int ma = 0; ma < 2; ma++) {
            ldsm_x4(afb[ma], aAddr[ma] + aoff);
            ldsm_x4(afs[ma], aAddr[ma] + aoff + (uint32_t)(NST * A_SZ) * 4u);
        }
#pragma unroll
        for (int pa = 0; pa < 4; pa++) {
            uint32_t bb[4], bs[4];
            ldsm_x4(bb, bAddr[pa] + boff);
            ldsm_x4(bs, bAddr[pa] + boff + (uint32_t)(NST * B_SZ) * 4u);
            const int n0 = 2 * pa, n1 = 2 * pa + 1;
            mma_f16(acc[0][n0], afb[0], bb[0], bb[1]);
            mma_f16(acc[1][n0], afb[1], bb[0], bb[1]);
            mma_f16(acc[0][n0], afb[0], bs[0], bs[1]);
            mma_f16(acc[1][n0], afb[1], bs[0], bs[1]);
            mma_f16(acc[0][n0], afs[0], bb[0], bb[1]);
            mma_f16(acc[1][n0], afs[1], bb[0], bb[1]);
            mma_f16(acc[0][n1], afb[0], bb[2], bb[3]);
            mma_f16(acc[1][n1], afb[1], bb[2], bb[3]);
            mma_f16(acc[0][n1], afb[0], bs[2], bs[3]);
            mma_f16(acc[1][n1], afb[1], bs[2], bs[3]);
            mma_f16(acc[0][n1], afs[0], bb[2], bb[3]);
            mma_f16(acc[1][n1], afs[1], bb[2], bb[3]);
        }

        if (kb + 1 < nk) { store_A(av, (kb + 1) % NST); av = av2; }
        if (deep) { CP_WAIT(1); } else { CP_WAIT(0); }
        __syncthreads();
    }

    // ---- epilogue ----
#pragma unroll
    for (int ma = 0; ma < 2; ma++) {
        int mrow0 = m0 + wm0 + ma * 16 + gid;
#pragma unroll
        for (int na = 0; na < 8; na++) {
            int n = wn0 + na * 8 + 2 * tig;
            float v0 = acc[ma][na][0], v1 = acc[ma][na][1];
            float v2 = acc[ma][na][2], v3 = acc[ma][na][3];
#pragma unroll
            for (int h = 0; h < 2; h++) {
                int m = mrow0 + h * 8;
                if (m >= M) continue;
                float a = h ? v2 : v0, b = h ? v3 : v1;
                int o = m * HDIM + n;
                if (MODE == 0) {
                    *(float2*)(out + o)  = make_float2(a, b);
                    *(float2*)(out2 + o) = make_float2(fmaxf(a, 0.f), fmaxf(b, 0.f));
                } else if (MODE == 1) {
                    float2 e = *(const float2*)(extra + o);
                    *(float2*)(out + o) =
                        make_float2(fmaxf(a + e.x, 0.f), fmaxf(b + e.y, 0.f));
                } else {
                    *(float2*)(out + o) =
                        make_float2(fmaxf(a + bias[n], 0.f), fmaxf(b + bias[n + 1], 0.f));
                }
            }
        }
    }
}

// ---------------------------------------------------------------------------
// Fused segment sum (blockIdx.y = graph). mol_idx sorted.
// ---------------------------------------------------------------------------
__global__ void segsum_kernel(const float* __restrict__ ah0, const int* __restrict__ mi0,
                              float* __restrict__ mh0,
                              const float* __restrict__ ah1, const int* __restrict__ mi1,
                              float* __restrict__ mh1, int n_atoms)
{
    const float* atom_h  = blockIdx.y ? ah1 : ah0;
    const int*   mol_idx = blockIdx.y ? mi1 : mi0;
    float*       mol_h   = blockIdx.y ? mh1 : mh0;
    const int m = blockIdx.x;
    const int t = threadIdx.x;
    int lo = 0, hi = n_atoms;
    while (lo < hi) { int mid = (lo + hi) >> 1; if (mol_idx[mid] < m) lo = mid + 1; else hi = mid; }
    int start = lo;
    hi = n_atoms;
    while (lo < hi) { int mid = (lo + hi) >> 1; if (mol_idx[mid] <= m) lo = mid + 1; else hi = mid; }
    int end = lo;
    float acc = 0.f;
    for (int a = start; a < end; a++) acc += atom_h[a * HDIM + t];
    mol_h[m * HDIM + t] = acc;
}

// ---------------------------------------------------------------------------
// Final MLP
// ---------------------------------------------------------------------------
__global__ void rxn_kernel(const float* __restrict__ src_mol,
                           const float* __restrict__ tgt_mol,
                           const float* __restrict__ Wrh,
                           const float* __restrict__ brh,
                           const float* __restrict__ Wro,
                           const float* __restrict__ bro,
                           float* __restrict__ out)
{
    __shared__ float diff[HDIM];
    __shared__ float red[HDIM];
    const int m = blockIdx.x;
    const int t = threadIdx.x;
    diff[t] = tgt_mol[m * HDIM + t] - src_mol[m * HDIM + t];
    __syncthreads();
    float s = 0.f;
    const float* wr = Wrh + t * HDIM;
#pragma unroll 8
    for (int k = 0; k < HDIM; k++) s = fmaf(diff[k], __ldg(wr + k), s);
    s = fmaxf(s + brh[t], 0.f);
    red[t] = s * Wro[t];
    __syncthreads();
    for (int o = 128; o > 0; o >>= 1) {
        if (t < o) red[t] += red[t + o];
        __syncthreads();
    }
    if (t == 0) out[m] = red[0] + bro[0];
}

// ---------------------------------------------------------------------------
// Host launcher
// ---------------------------------------------------------------------------
extern "C" void kernel_launch(void* const* d_in, const int* in_sizes, int n_in,
                              void* d_out, int out_size)
{
    const float* fatoms[2]  = { (const float*)d_in[0], (const float*)d_in[5] };
    const float* fbonds[2]  = { (const float*)d_in[1], (const float*)d_in[6] };
    const int*   agraph[2]  = { (const int*)d_in[2],   (const int*)d_in[7] };
    const int*   bgraph[2]  = { (const int*)d_in[3],   (const int*)d_in[8] };
    const int*   mol_idx[2] = { (const int*)d_in[4],   (const int*)d_in[9] };
    const float* Wi[2] = { (const float*)d_in[10], (const float*)d_in[14] };
    const float* Wh[2] = { (const float*)d_in[11], (const float*)d_in[15] };
    const float* Wo[2] = { (const float*)d_in[12], (const float*)d_in[16] };
    const float* bo[2] = { (const float*)d_in[13], (const float*)d_in[17] };
    const float* Wrh = (const float*)d_in[18];
    const float* brh = (const float*)d_in[19];
    const float* Wro = (const float*)d_in[20];
    const float* bro = (const float*)d_in[21];

    const int n_atoms = in_sizes[0] / 82;
    const int n_bonds = in_sizes[1] / 88;
    const int max_nei = in_sizes[2] / n_atoms;

    cudaFuncSetAttribute(h16_gemm_kernel<0>,
                         cudaFuncAttributeMaxDynamicSharedMemorySize, SMEM_BYTES);
    cudaFuncSetAttribute(h16_gemm_kernel<1>,
                         cudaFuncAttributeMaxDynamicSharedMemorySize, SMEM_BYTES);
    cudaFuncSetAttribute(h16_gemm_kernel<2>,
                         cudaFuncAttributeMaxDynamicSharedMemorySize, SMEM_BYTES);

    float *nih, *msgA, *msgB, *mol;
    __half *Wbb, *Wss;
    cudaGetSymbolAddress((void**)&nih,  g_nih);
    cudaGetSymbolAddress((void**)&msgA, g_msgA);
    cudaGetSymbolAddress((void**)&msgB, g_msgB);
    cudaGetSymbolAddress((void**)&mol,  g_mol);
    cudaGetSymbolAddress((void**)&Wbb, g_Wb);
    cudaGetSymbolAddress((void**)&Wss, g_Ws);

    const size_t GSTR = (size_t)MAXB * HDIM;
    const int MS = 256 * WSTR;

    dim3 gSplit((256 * WSTR + 255) / 256, 6);
    split_all_w_kernel<<<gSplit, 256>>>(Wi[0], Wh[0], Wo[0], Wi[1], Wh[1], Wo[1],
                                        Wbb, Wss);

    const int gB = (n_bonds + BM - 1) / BM;
    const int gA = (n_atoms + BM - 1) / BM;

    GArgs in0, in1, mp0, mp1, ou0, ou1;
    // ---- input GEMM args ----
    for (int g = 0; g < 2; g++) {
        GArgs a;
        a.src = fbonds[g]; a.graph = nullptr;
        a.Wb = Wbb + (3*g+0)*MS; a.Ws = Wss + (3*g+0)*MS;
        a.extra = nullptr; a.bias = nullptr;
        a.out = nih + g * GSTR; a.out2 = msgA + g * GSTR; a.M = n_bonds;
        if (g == 0) in0 = a; else in1 = a;
    }
    h16_gemm_kernel<0><<<2 * gB, 512, SMEM_BYTES>>>(in0, in1, gB, 6, 88, max_nei);

    // ---- 3 MP iterations (both graphs per launch) ----
    float* bufs[2][2] = { { msgA, msgA + GSTR }, { msgB, msgB + GSTR } };
    int cur = 0;
    for (int d = 0; d < 3; d++) {
        for (int g = 0; g < 2; g++) {
            GArgs a;
            a.src = bufs[cur][g]; a.graph = bgraph[g];
            a.Wb = Wbb + (3*g+1)*MS; a.Ws = Wss + (3*g+1)*MS;
            a.extra = nih + g * GSTR; a.bias = nullptr;
            a.out = bufs[1 - cur][g]; a.out2 = nullptr; a.M = n_bonds;
            if (g == 0) mp0 = a; else mp1 = a;
        }
        h16_gemm_kernel<1><<<2 * gB, 512, SMEM_BYTES>>>(mp0, mp1, gB, 16, 256, max_nei);
        cur = 1 - cur;
    }

    // ---- output GEMM (atom_h aliases nih per graph) ----
    for (int g = 0; g < 2; g++) {
        GArgs a;
        a.src = bufs[cur][g]; a.graph = agraph[g];
        a.Wb = Wbb + (3*g+2)*MS; a.Ws = Wss + (3*g+2)*MS;
        a.extra = fatoms[g]; a.bias = bo[g];
        a.out = nih + g * GSTR; a.out2 = nullptr; a.M = n_atoms;
        if (g == 0) ou0 = a; else ou1 = a;
    }
    h16_gemm_kernel<2><<<2 * gA, 512, SMEM_BYTES>>>(ou0, ou1, gA, 22, 338, max_nei);

    // ---- fused pooling + final MLP ----
    segsum_kernel<<<dim3(NMOLS, 2), 256>>>(nih, mol_idx[0], mol,
                                           nih + GSTR, mol_idx[1],
                                           mol + NMOLS * HDIM, n_atoms);
    rxn_kernel<<<NMOLS, 256>>>(mol, mol + NMOLS * HDIM,
                               Wrh, brh, Wro, bro, (float*)d_out);
}

// round 12
// speedup vs baseline: 1.0701x; 1.0701x over previous
#include <cuda_runtime.h>
#include <cuda_fp16.h>
#include <cstdint>

// ---------------------------------------------------------------------------
// RxnPredictor: dual D-MPNN graph conv + mol pooling + reaction MLP
// R11: R9's proven GEMM inner loop (2-stage double-buffer + register
// prefetch + ldmatrix), with src/tgt graphs fused per launch (15 -> 8).
// ---------------------------------------------------------------------------

#define MAXB  200000
#define HDIM  256
#define NMOLS 2048
#define NEI   10
#define WSTR  352          // padded K stride for pre-split weights

__device__ float g_nih [2][MAXB * HDIM];
__device__ float g_msgA[2][MAXB * HDIM];
__device__ float g_msgB[2][MAXB * HDIM];
__device__ float g_mol [2][NMOLS * HDIM];
__device__ __half g_Wb[6 * 256 * WSTR];   // big halves, 6 matrices
__device__ __half g_Ws[6 * 256 * WSTR];   // small halves

struct GArgs {
    const float* src; const int* graph;
    const __half* Wb; const __half* Ws;
    const float* extra; const float* bias;
    float* out; float* out2; int M;
};

// ---------------------------------------------------------------------------
// helpers
// ---------------------------------------------------------------------------
__device__ __forceinline__ uint32_t pack_h2(__half lo, __half hi) {
    __half2 h = __halves2half2(lo, hi);
    return *reinterpret_cast<uint32_t*>(&h);
}
__device__ __forceinline__ void split2(float x, float y, uint32_t& b, uint32_t& s) {
    __half hx = __float2half_rn(x), hy = __float2half_rn(y);
    float rx = x - __half2float(hx), ry = y - __half2float(hy);
    b = pack_h2(hx, hy);
    s = pack_h2(__float2half_rn(rx), __float2half_rn(ry));
}
__device__ __forceinline__ void mma_f16(float* d, const uint32_t* a,
                                        uint32_t b0, uint32_t b1) {
    asm volatile(
        "mma.sync.aligned.m16n8k16.row.col.f32.f16.f16.f32 "
        "{%0,%1,%2,%3}, {%4,%5,%6,%7}, {%8,%9}, {%0,%1,%2,%3};"
        : "+f"(d[0]), "+f"(d[1]), "+f"(d[2]), "+f"(d[3])
        : "r"(a[0]), "r"(a[1]), "r"(a[2]), "r"(a[3]), "r"(b0), "r"(b1));
}
__device__ __forceinline__ void ldsm_x4(uint32_t* r, uint32_t addr) {
    asm volatile("ldmatrix.sync.aligned.m8n8.x4.shared.b16 {%0,%1,%2,%3}, [%4];"
                 : "=r"(r[0]), "=r"(r[1]), "=r"(r[2]), "=r"(r[3]) : "r"(addr));
}
__device__ __forceinline__ uint32_t smem_u32(const void* p) {
    uint32_t a;
    asm("{ .reg .u64 t; cvta.to.shared.u64 t, %1; cvt.u32.u64 %0, t; }"
        : "=r"(a) : "l"(p));
    return a;
}

// ---------------------------------------------------------------------------
// Fused weight pre-split (slots 0..5 = Wi_s,Wh_s,Wo_s,Wi_t,Wh_t,Wo_t).
// Wo permutation: [gather(256) | fatoms(82)].
// ---------------------------------------------------------------------------
__global__ void split_all_w_kernel(const float* __restrict__ Wi_s, const float* __restrict__ Wh_s,
                                   const float* __restrict__ Wo_s, const float* __restrict__ Wi_t,
                                   const float* __restrict__ Wh_t, const float* __restrict__ Wo_t,
                                   __half* __restrict__ Wb, __half* __restrict__ Ws)
{
    const int slot = blockIdx.y;
    int i = blockIdx.x * 256 + threadIdx.x;
    if (i >= 256 * WSTR) return;
    int n = i / WSTR, k = i % WSTR;
    const float* W; int Ksrc; int perm;
    switch (slot) {
        case 0: W = Wi_s; Ksrc = 88;  perm = 0; break;
        case 1: W = Wh_s; Ksrc = 256; perm = 0; break;
        case 2: W = Wo_s; Ksrc = 338; perm = 1; break;
        case 3: W = Wi_t; Ksrc = 88;  perm = 0; break;
        case 4: W = Wh_t; Ksrc = 256; perm = 0; break;
        default: W = Wo_t; Ksrc = 338; perm = 1; break;
    }
    float v = 0.f;
    if (perm) {
        if (k < 256)      v = W[n * 338 + 82 + k];
        else if (k < 338) v = W[n * 338 + (k - 256)];
    } else if (k < Ksrc) {
        v = W[n * Ksrc + k];
    }
    __half hb = __float2half_rn(v);
    size_t o = (size_t)slot * 256 * WSTR + i;
    Wb[o] = hb;
    Ws[o] = __float2half_rn(v - __half2float(hb));
}

// ---------------------------------------------------------------------------
// 3xFP16 GEMM (R9 inner loop), dual-graph fused dispatch.
// Block 512 thr, BM=128, BN=256, BK=16, double-buffered smem + reg prefetch.
// Fragments via ldmatrix.x4 (conflict-free, 48B row stride).
// MODE 0: dense A (Kd=88); MODE 1: gather (K=256); MODE 2: [gather|fatoms].
// ---------------------------------------------------------------------------
#define BM 128
#define AROW 12
#define A_SZ (BM * AROW)
#define B_SZ (256 * AROW)
#define A_BIG(st) ((st) * A_SZ)
#define A_SML(st) (2 * A_SZ + (st) * A_SZ)
#define B_BIG(st) (4 * A_SZ + (st) * B_SZ)
#define B_SML(st) (4 * A_SZ + 2 * B_SZ + (st) * B_SZ)
#define SIDX_OFF  (4 * A_SZ + 4 * B_SZ)
#define SMEM_U32  (SIDX_OFF + BM * NEI)
#define SMEM_BYTES (SMEM_U32 * 4)

template <int MODE>
__global__ __launch_bounds__(512)
void h16_gemm_kernel(GArgs ga0, GArgs ga1, int nblk0, int nk, int Kd, int max_nei)
{
    extern __shared__ uint32_t SM[];
    int* sIdx = (int*)(SM + SIDX_OFF);

    const bool second = (blockIdx.x >= (unsigned)nblk0);
    const GArgs G = second ? ga1 : ga0;
    const int bx = second ? (blockIdx.x - nblk0) : blockIdx.x;
    const float* __restrict__ src   = G.src;
    const int*   __restrict__ graph = G.graph;
    const __half* __restrict__ Wb   = G.Wb;
    const __half* __restrict__ Ws   = G.Ws;
    const float* __restrict__ extra = G.extra;
    const float* __restrict__ bias  = G.bias;
    float* __restrict__ out  = G.out;
    float* __restrict__ out2 = G.out2;
    const int M = G.M;

    const int t    = threadIdx.x;
    const int lane = t & 31;
    const int wid  = t >> 5;
    const int gid  = lane >> 2;
    const int tig  = lane & 3;
    const int wm0  = (wid & 3) * 32;  // 4 m-warps
    const int wn0  = (wid >> 2) * 64; // 4 n-warps
    const int m0   = bx * BM;
    const int r    = t >> 2;          // A row (0..127)
    const int q    = t & 3;           // A k-quad
    const int bnn  = t >> 1;          // B row (0..255)
    const int bpt  = t & 1;           // B half-row part

    if (MODE != 0) {
        for (int i = t; i < BM * NEI; i += 512) {
            int rr = i / NEI, j = i % NEI;
            int m = m0 + rr;
            sIdx[i] = (m < M && j < max_nei) ? graph[m * max_nei + j] : -1;
        }
    }
    __syncthreads();

    // ---- ldmatrix lane addresses (stage-0; toggled by offset) ----
    const uint32_t smbase = smem_u32(SM);
    const int g8 = lane & 7;
    uint32_t aAddr[2];
#pragma unroll
    for (int ma = 0; ma < 2; ma++) {
        int row = wm0 + ma * 16 + g8 + ((lane >> 3) & 1) * 8;
        int byo = ((lane >> 4) & 1) * 16;
        aAddr[ma] = smbase + (uint32_t)(row * AROW) * 4u + byo;
    }
    uint32_t bAddr[4];
#pragma unroll
    for (int pa = 0; pa < 4; pa++) {
        int col = wn0 + pa * 16 + ((lane >> 4) & 1) * 8 + g8;
        int byo = ((lane >> 3) & 1) * 16;
        bAddr[pa] = smbase + (uint32_t)(B_BIG(0) + col * AROW) * 4u + byo;
    }

    float acc[2][8][4];
#pragma unroll
    for (int a = 0; a < 2; a++)
#pragma unroll
        for (int b = 0; b < 8; b++)
#pragma unroll
            for (int c = 0; c < 4; c++) acc[a][b][c] = 0.f;

    float4 av;           // A prefetch (fp32, split at store)
    uint4  bvb, bvs;     // B prefetch (pre-split halves)

    auto load_tile = [&](int kb) {
        const int k0 = kb * 16;
        av = make_float4(0.f, 0.f, 0.f, 0.f);
        const int m = m0 + r;
        if (m < M) {
            if (MODE == 0) {
                const int k = k0 + q * 4;
                if (k + 3 < Kd)
                    av = *(const float4*)(src + (size_t)m * Kd + k);
            } else if (MODE == 1 || (MODE == 2 && k0 < 256)) {
                const float4* bp = (const float4*)src + (k0 >> 2) + q;
                const int* ip = sIdx + r * NEI;
                float4 v0, v1, v2, v3, v4;
#pragma unroll
                for (int w = 0; w < 2; w++) {
                    int s0 = ip[w * 5 + 0], s1 = ip[w * 5 + 1], s2 = ip[w * 5 + 2];
                    int s3 = ip[w * 5 + 3], s4 = ip[w * 5 + 4];
                    v0 = (s0 >= 0) ? bp[s0 * 64] : make_float4(0, 0, 0, 0);
                    v1 = (s1 >= 0) ? bp[s1 * 64] : make_float4(0, 0, 0, 0);
                    v2 = (s2 >= 0) ? bp[s2 * 64] : make_float4(0, 0, 0, 0);
                    v3 = (s3 >= 0) ? bp[s3 * 64] : make_float4(0, 0, 0, 0);
                    v4 = (s4 >= 0) ? bp[s4 * 64] : make_float4(0, 0, 0, 0);
                    av.x += v0.x + v1.x + v2.x + v3.x + v4.x;
                    av.y += v0.y + v1.y + v2.y + v3.y + v4.y;
                    av.z += v0.z + v1.z + v2.z + v3.z + v4.z;
                    av.w += v0.w + v1.w + v2.w + v3.w + v4.w;
                }
            } else {  // MODE 2 tail: fatoms columns (k-256 < 82)
                float tmpv[4];
#pragma unroll
                for (int c = 0; c < 4; c++) {
                    int kk = k0 + q * 4 + c - 256;
                    tmpv[c] = (kk < 82) ? extra[m * 82 + kk] : 0.f;
                }
                av = make_float4(tmpv[0], tmpv[1], tmpv[2], tmpv[3]);
            }
        }
        // B: pre-split halves, padded stride -> unconditional LDG.128
        const size_t bo = (size_t)bnn * WSTR + k0 + bpt * 8;
        bvb = *(const uint4*)(Wb + bo);
        bvs = *(const uint4*)(Ws + bo);
    };

    auto store_tile = [&](int st) {
        uint32_t* Ab = SM + A_BIG(st);
        uint32_t* As = SM + A_SML(st);
        uint32_t* Bb = SM + B_BIG(st);
        uint32_t* Bs = SM + B_SML(st);
        uint32_t b0, s0, b1, s1;
        split2(av.x, av.y, b0, s0);
        split2(av.z, av.w, b1, s1);
        *(uint2*)&Ab[r * AROW + q * 2] = make_uint2(b0, b1);
        *(uint2*)&As[r * AROW + q * 2] = make_uint2(s0, s1);
        *(uint4*)&Bb[bnn * AROW + bpt * 4] = bvb;
        *(uint4*)&Bs[bnn * AROW + bpt * 4] = bvs;
    };

    load_tile(0);
    store_tile(0);
    __syncthreads();

    int cur = 0;
    for (int kb = 0; kb < nk; kb++) {
        const bool pf = (kb + 1 < nk);
        if (pf) load_tile(kb + 1);

        const uint32_t aoff = (uint32_t)cur * (A_SZ * 4u);
        const uint32_t boff = (uint32_t)cur * (B_SZ * 4u);

        uint32_t afb[2][4], afs[2][4];
#pragma unroll
        for (int ma = 0; ma < 2; ma++) {
            ldsm_x4(afb[ma], aAddr[ma] + aoff);
            ldsm_x4(afs[ma], aAddr[ma] + aoff + 2u * A_SZ * 4u);
        }
#pragma unroll
        for (int pa = 0; pa < 4; pa++) {
            uint32_t bb[4], bs[4];
            ldsm_x4(bb, bAddr[pa] + boff);
            ldsm_x4(bs, bAddr[pa] + boff + 2u * B_SZ * 4u);
            const int n0 = 2 * pa, n1 = 2 * pa + 1;
            mma_f16(acc[0][n0], afb[0], bb[0], bb[1]);   // big*big
            mma_f16(acc[1][n0], afb[1], bb[0], bb[1]);
            mma_f16(acc[0][n0], afb[0], bs[0], bs[1]);   // big*small
            mma_f16(acc[1][n0], afb[1], bs[0], bs[1]);
            mma_f16(acc[0][n0], afs[0], bb[0], bb[1]);   // small*big
            mma_f16(acc[1][n0], afs[1], bb[0], bb[1]);
            mma_f16(acc[0][n1], afb[0], bb[2], bb[3]);
            mma_f16(acc[1][n1], afb[1], bb[2], bb[3]);
            mma_f16(acc[0][n1], afb[0], bs[2], bs[3]);
            mma_f16(acc[1][n1], afb[1], bs[2], bs[3]);
            mma_f16(acc[0][n1], afs[0], bb[2], bb[3]);
            mma_f16(acc[1][n1], afs[1], bb[2], bb[3]);
        }

        if (pf) store_tile(cur ^ 1);
        __syncthreads();
        cur ^= 1;
    }

    // ---- epilogue ----
#pragma unroll
    for (int ma = 0; ma < 2; ma++) {
        int mrow0 = m0 + wm0 + ma * 16 + gid;
#pragma unroll
        for (int na = 0; na < 8; na++) {
            int n = wn0 + na * 8 + 2 * tig;
            float v0 = acc[ma][na][0], v1 = acc[ma][na][1];
            float v2 = acc[ma][na][2], v3 = acc[ma][na][3];
#pragma unroll
            for (int h = 0; h < 2; h++) {
                int m = mrow0 + h * 8;
                if (m >= M) continue;
                float a = h ? v2 : v0, b = h ? v3 : v1;
                int o = m * HDIM + n;
                if (MODE == 0) {
                    *(float2*)(out + o)  = make_float2(a, b);
                    *(float2*)(out2 + o) = make_float2(fmaxf(a, 0.f), fmaxf(b, 0.f));
                } else if (MODE == 1) {
                    float2 e = *(const float2*)(extra + o);
                    *(float2*)(out + o) =
                        make_float2(fmaxf(a + e.x, 0.f), fmaxf(b + e.y, 0.f));
                } else {
                    *(float2*)(out + o) =
                        make_float2(fmaxf(a + bias[n], 0.f), fmaxf(b + bias[n + 1], 0.f));
                }
            }
        }
    }
}

// ---------------------------------------------------------------------------
// Fused segment sum (blockIdx.y = graph). mol_idx sorted.
// ---------------------------------------------------------------------------
__global__ void segsum_kernel(const float* __restrict__ ah0, const int* __restrict__ mi0,
                              float* __restrict__ mh0,
                              const float* __restrict__ ah1, const int* __restrict__ mi1,
                              float* __restrict__ mh1, int n_atoms)
{
    const float* atom_h  = blockIdx.y ? ah1 : ah0;
    const int*   mol_idx = blockIdx.y ? mi1 : mi0;
    float*       mol_h   = blockIdx.y ? mh1 : mh0;
    const int m = blockIdx.x;
    const int t = threadIdx.x;
    int lo = 0, hi = n_atoms;
    while (lo < hi) { int mid = (lo + hi) >> 1; if (mol_idx[mid] < m) lo = mid + 1; else hi = mid; }
    int start = lo;
    hi = n_atoms;
    while (lo < hi) { int mid = (lo + hi) >> 1; if (mol_idx[mid] <= m) lo = mid + 1; else hi = mid; }
    int end = lo;
    float acc = 0.f;
    for (int a = start; a < end; a++) acc += atom_h[a * HDIM + t];
    mol_h[m * HDIM + t] = acc;
}

// ---------------------------------------------------------------------------
// Final MLP
// ---------------------------------------------------------------------------
__global__ void rxn_kernel(const float* __restrict__ src_mol,
                           const float* __restrict__ tgt_mol,
                           const float* __restrict__ Wrh,
                           const float* __restrict__ brh,
                           const float* __restrict__ Wro,
                           const float* __restrict__ bro,
                           float* __restrict__ out)
{
    __shared__ float diff[HDIM];
    __shared__ float red[HDIM];
    const int m = blockIdx.x;
    const int t = threadIdx.x;
    diff[t] = tgt_mol[m * HDIM + t] - src_mol[m * HDIM + t];
    __syncthreads();
    float s = 0.f;
    const float* wr = Wrh + t * HDIM;
#pragma unroll 8
    for (int k = 0; k < HDIM; k++) s = fmaf(diff[k], __ldg(wr + k), s);
    s = fmaxf(s + brh[t], 0.f);
    red[t] = s * Wro[t];
    __syncthreads();
    for (int o = 128; o > 0; o >>= 1) {
        if (t < o) red[t] += red[t + o];
        __syncthreads();
    }
    if (t == 0) out[m] = red[0] + bro[0];
}

// ---------------------------------------------------------------------------
// Host launcher
// ---------------------------------------------------------------------------
extern "C" void kernel_launch(void* const* d_in, const int* in_sizes, int n_in,
                              void* d_out, int out_size)
{
    const float* fatoms[2]  = { (const float*)d_in[0], (const float*)d_in[5] };
    const float* fbonds[2]  = { (const float*)d_in[1], (const float*)d_in[6] };
    const int*   agraph[2]  = { (const int*)d_in[2],   (const int*)d_in[7] };
    const int*   bgraph[2]  = { (const int*)d_in[3],   (const int*)d_in[8] };
    const int*   mol_idx[2] = { (const int*)d_in[4],   (const int*)d_in[9] };
    const float* Wi[2] = { (const float*)d_in[10], (const float*)d_in[14] };
    const float* Wh[2] = { (const float*)d_in[11], (const float*)d_in[15] };
    const float* Wo[2] = { (const float*)d_in[12], (const float*)d_in[16] };
    const float* bo[2] = { (const float*)d_in[13], (const float*)d_in[17] };
    const float* Wrh = (const float*)d_in[18];
    const float* brh = (const float*)d_in[19];
    const float* Wro = (const float*)d_in[20];
    const float* bro = (const float*)d_in[21];

    const int n_atoms = in_sizes[0] / 82;
    const int n_bonds = in_sizes[1] / 88;
    const int max_nei = in_sizes[2] / n_atoms;

    cudaFuncSetAttribute(h16_gemm_kernel<0>,
                         cudaFuncAttributeMaxDynamicSharedMemorySize, SMEM_BYTES);
    cudaFuncSetAttribute(h16_gemm_kernel<1>,
                         cudaFuncAttributeMaxDynamicSharedMemorySize, SMEM_BYTES);
    cudaFuncSetAttribute(h16_gemm_kernel<2>,
                         cudaFuncAttributeMaxDynamicSharedMemorySize, SMEM_BYTES);

    float *nih, *msgA, *msgB, *mol;
    __half *Wbb, *Wss;
    cudaGetSymbolAddress((void**)&nih,  g_nih);
    cudaGetSymbolAddress((void**)&msgA, g_msgA);
    cudaGetSymbolAddress((void**)&msgB, g_msgB);
    cudaGetSymbolAddress((void**)&mol,  g_mol);
    cudaGetSymbolAddress((void**)&Wbb, g_Wb);
    cudaGetSymbolAddress((void**)&Wss, g_Ws);

    const size_t GSTR = (size_t)MAXB * HDIM;
    const int MS = 256 * WSTR;

    dim3 gSplit((256 * WSTR + 255) / 256, 6);
    split_all_w_kernel<<<gSplit, 256>>>(Wi[0], Wh[0], Wo[0], Wi[1], Wh[1], Wo[1],
                                        Wbb, Wss);

    const int gB = (n_bonds + BM - 1) / BM;
    const int gA = (n_atoms + BM - 1) / BM;

    GArgs in0, in1, mp0, mp1, ou0, ou1;
    // ---- input GEMM args ----
    for (int g = 0; g < 2; g++) {
        GArgs a;
        a.src = fbonds[g]; a.graph = nullptr;
        a.Wb = Wbb + (3*g+0)*MS; a.Ws = Wss + (3*g+0)*MS;
        a.extra = nullptr; a.bias = nullptr;
        a.out = nih + g * GSTR; a.out2 = msgA + g * GSTR; a.M = n_bonds;
        if (g == 0) in0 = a; else in1 = a;
    }
    h16_gemm_kernel<0><<<2 * gB, 512, SMEM_BYTES>>>(in0, in1, gB, 6, 88, max_nei);

    // ---- 3 MP iterations (both graphs per launch) ----
    float* bufs[2][2] = { { msgA, msgA + GSTR }, { msgB, msgB + GSTR } };
    int cur = 0;
    for (int d = 0; d < 3; d++) {
        for (int g = 0; g < 2; g++) {
            GArgs a;
            a.src = bufs[cur][g]; a.graph = bgraph[g];
            a.Wb = Wbb + (3*g+1)*MS; a.Ws = Wss + (3*g+1)*MS;
            a.extra = nih + g * GSTR; a.bias = nullptr;
            a.out = bufs[1 - cur][g]; a.out2 = nullptr; a.M = n_bonds;
            if (g == 0) mp0 = a; else mp1 = a;
        }
        h16_gemm_kernel<1><<<2 * gB, 512, SMEM_BYTES>>>(mp0, mp1, gB, 16, 256, max_nei);
        cur = 1 - cur;
    }

    // ---- output GEMM (atom_h aliases nih per graph) ----
    for (int g = 0; g < 2; g++) {
        GArgs a;
        a.src = bufs[cur][g]; a.graph = agraph[g];
        a.Wb = Wbb + (3*g+2)*MS; a.Ws = Wss + (3*g+2)*MS;
        a.extra = fatoms[g]; a.bias = bo[g];
        a.out = nih + g * GSTR; a.out2 = nullptr; a.M = n_atoms;
        if (g == 0) ou0 = a; else ou1 = a;
    }
    h16_gemm_kernel<2><<<2 * gA, 512, SMEM_BYTES>>>(ou0, ou1, gA, 22, 338, max_nei);

    // ---- fused pooling + final MLP ----
    segsum_kernel<<<dim3(NMOLS, 2), 256>>>(nih, mol_idx[0], mol,
                                           nih + GSTR, mol_idx[1],
                                           mol + NMOLS * HDIM, n_atoms);
    rxn_kernel<<<NMOLS, 256>>>(mol, mol + NMOLS * HDIM,
                               Wrh, brh, Wro, bro, (float*)d_out);
}